// round 12
// baseline (speedup 1.0000x reference)
#include <cuda_runtime.h>
#include <cuda_bf16.h>
#include <cstdint>

// Shapes (fixed)
#define BATCH   16
#define SEQ     2048
#define M_ROWS  (BATCH * SEQ)   // 32768
#define KDIM    1024
#define NDIM    1024

// GEMM tiling: block 128x128, 4 warps (warp tile 64x64), BK=32, 3-stage pipe
#define BK          32
#define NCHUNKS     (KDIM / BK)         // 32
#define NST         3
#define A_STAGE_B   16384               // 128 rows * 128B (canonical, swizzled)
#define B_STAGE_B   16384               // 8 pairs * 4 kb * 32 lanes * 16B
#define STAGE_B     (A_STAGE_B + B_STAGE_B)   // 32768
#define BAR_OFF     (NST * STAGE_B)           // 98304: full[0..2], empty[0..2]
#define SMEM_BYTES  (BAR_OFF + 64)

// ---------------- scratch -----------------------------------------------
__device__ float g_wpf[NDIM * KDIM];               // Wp tf32, B-pair-frag-major
__device__ float g_wvf[NDIM * KDIM];               // Wv tf32, B-pair-frag-major
__device__ __nv_bfloat16 g_xp[(size_t)M_ROWS * NDIM];  // xp in bf16
__device__ float g_ss [M_ROWS];
__device__ float g_inv[M_ROWS];
__device__ float g_ws [BATCH * NDIM];
__device__ float g_att[M_ROWS];
__device__ float g_msum[BATCH];

// ---------------- helpers ------------------------------------------------
__device__ __forceinline__ uint32_t smem_u32(const void* p) {
    uint32_t a;
    asm("{ .reg .u64 t; cvta.to.shared.u64 t, %1; cvt.u32.u64 %0, t; }" : "=r"(a) : "l"(p));
    return a;
}
__device__ __forceinline__ void mma_tf32(float c[4], const uint32_t a[4], const uint32_t b[2]) {
    asm volatile(
        "mma.sync.aligned.m16n8k8.row.col.f32.tf32.tf32.f32 "
        "{%0,%1,%2,%3}, {%4,%5,%6,%7}, {%8,%9}, {%0,%1,%2,%3};\n"
        : "+f"(c[0]), "+f"(c[1]), "+f"(c[2]), "+f"(c[3])
        : "r"(a[0]), "r"(a[1]), "r"(a[2]), "r"(a[3]), "r"(b[0]), "r"(b[1]));
}
__device__ __forceinline__ void ldsm4(uint32_t a[4], uint32_t addr) {
    asm volatile("ldmatrix.sync.aligned.m8n8.x4.shared.b16 {%0,%1,%2,%3}, [%4];"
        : "=r"(a[0]), "=r"(a[1]), "=r"(a[2]), "=r"(a[3]) : "r"(addr));
}
__device__ __forceinline__ void cp16(uint32_t dst, const void* src) {
    asm volatile("cp.async.cg.shared.global [%0], [%1], 16;" :: "r"(dst), "l"(src) : "memory");
}
__device__ __forceinline__ void cpasync_arrive(uint32_t mbar) {
    asm volatile("cp.async.mbarrier.arrive.noinc.shared.b64 [%0];" :: "r"(mbar) : "memory");
}
__device__ __forceinline__ void mbar_init(uint32_t mbar, uint32_t cnt) {
    asm volatile("mbarrier.init.shared.b64 [%0], %1;" :: "r"(mbar), "r"(cnt) : "memory");
}
__device__ __forceinline__ void mbar_arrive(uint32_t mbar) {
    asm volatile("mbarrier.arrive.shared.b64 _, [%0];" :: "r"(mbar) : "memory");
}
__device__ __forceinline__ void mbar_wait(uint32_t mbar, uint32_t parity) {
    asm volatile(
        "{ .reg .pred P;\nWL_%=:\n"
        "mbarrier.try_wait.parity.acquire.cta.shared::cta.b64 P, [%0], %1, 0x989680;\n"
        "@P bra.uni WD_%=;\nbra.uni WL_%=;\nWD_%=:\n}"
        :: "r"(mbar), "r"(parity) : "memory");
}
__device__ __forceinline__ float rna_tf32(float x) {
    asm("cvt.rna.tf32.f32 %0, %0;" : "+f"(x));
    return x;
}

// ---------------- mbarrier-pipelined tf32 GEMM ---------------------------
// A: canonical [M,K] fp32 (x itself), SW128-swizzled rows, ldmatrix frags.
// B: pair-frag-major prepass (rna), float4 loads.
template<bool SCALE>
__global__ __launch_bounds__(128, 2) void gemm_relu_kernel(
    const float* __restrict__ A,
    const float* __restrict__ Bf,
    const float* __restrict__ bias,
    float* __restrict__ Cout)
{
    extern __shared__ float smemf[];
    const uint32_t sb = smem_u32(smemf);

    const int tid    = threadIdx.x;
    const int warpId = tid >> 5;
    const int lane   = tid & 31;
    const int wm     = warpId >> 1;   // 0..1
    const int wn     = warpId & 1;    // 0..1
    const int g      = lane >> 2;
    const int tg     = lane & 3;

    const int rowBlock = blockIdx.y * 128;
    const int colBlock = blockIdx.x * 128;
    const int p8base   = colBlock >> 4;

    const int roff  = (lane & 7) + (((lane >> 3) & 1) << 3);
    const int coff  = lane >> 4;
    const uint32_t xorm = (lane & 7) << 4;
    const uint32_t a_lane_base = (uint32_t)(wm * 64 + roff) * 128;

    const uint32_t fullb  = sb + BAR_OFF;        // full[s]  = +s*8
    const uint32_t emptyb = sb + BAR_OFF + 24;   // empty[s] = +s*8

    if (tid == 0) {
        #pragma unroll
        for (int s = 0; s < NST; s++) {
            mbar_init(fullb  + s * 8, 128);
            mbar_init(emptyb + s * 8, 4);
        }
    }
    __syncthreads();

    float acc[4][8][4];
    #pragma unroll
    for (int mi = 0; mi < 4; mi++)
        #pragma unroll
        for (int ni = 0; ni < 8; ni++)
            #pragma unroll
            for (int r = 0; r < 4; r++) acc[mi][ni][r] = 0.f;

    auto load_stage = [&](int ck, int slot) {
        const uint32_t base = sb + slot * STAGE_B;
        const int kf0 = ck * BK;
        #pragma unroll
        for (int j = 0; j < 8; j++) {       // A: canonical rows, swizzled
            const int i   = tid + j * 128;
            const int row = i >> 3;
            const int kc  = i & 7;
            const uint32_t dst = base + (uint32_t)row * 128 + (((uint32_t)kc << 4) ^ ((row & 7) << 4));
            cp16(dst, A + (size_t)(rowBlock + row) * KDIM + kf0 + kc * 4);
        }
        const int kb0 = ck * 4;
        #pragma unroll
        for (int j = 0; j < 8; j++) {       // B: frag-major
            const int i   = tid + j * 128;
            const int pl  = i >> 7;
            const int kbl = (i >> 5) & 3;
            const int ln  = i & 31;
            const size_t src = ((size_t)((p8base + pl) * 128 + kb0 + kbl) * 32 + ln) * 4;
            cp16(base + A_STAGE_B + i * 16, Bf + src);
        }
        cpasync_arrive(fullb + slot * 8);
    };

    load_stage(0, 0);
    load_stage(1, 1);

    for (int ks = 0; ks < NCHUNKS; ks++) {
        const int slot = ks % NST;
        mbar_wait(fullb + slot * 8, (ks / NST) & 1);   // stage ks data ready (all threads)

        const uint32_t sAu = sb + slot * STAGE_B + a_lane_base;
        const float* sB = smemf + slot * (STAGE_B / 4) + (A_STAGE_B / 4);

        uint32_t af[4][4];
        uint32_t bf[8][2];
        #pragma unroll
        for (int mi = 0; mi < 4; mi++)
            ldsm4(af[mi], sAu + (uint32_t)(mi * 16) * 128 + (((uint32_t)coff << 4) ^ xorm));
        #pragma unroll
        for (int pi = 0; pi < 4; pi++) {
            const float4 v = *(const float4*)&sB[(((wn * 4 + pi) * 4 + 0) * 32 + lane) * 4];
            bf[2 * pi][0]     = __float_as_uint(v.x); bf[2 * pi][1]     = __float_as_uint(v.y);
            bf[2 * pi + 1][0] = __float_as_uint(v.z); bf[2 * pi + 1][1] = __float_as_uint(v.w);
        }

        if (ks + 2 < NCHUNKS) {
            const int sk = ks + 2, ps = sk % NST, r = sk / NST;
            if (r >= 1) mbar_wait(emptyb + ps * 8, (r - 1) & 1);  // slot consumed
            load_stage(sk, ps);
        }

        #pragma unroll
        for (int kb = 0; kb < 4; kb++) {
            #pragma unroll
            for (int mi = 0; mi < 4; mi++)
                #pragma unroll
                for (int ni = 0; ni < 8; ni++)
                    mma_tf32(acc[mi][ni], af[mi], bf[ni]);
            if (kb < 3) {
                const uint32_t kin = (((uint32_t)(kb + 1) << 5) | ((uint32_t)coff << 4)) ^ xorm;
                #pragma unroll
                for (int mi = 0; mi < 4; mi++)
                    ldsm4(af[mi], sAu + (uint32_t)(mi * 16) * 128 + kin);
                #pragma unroll
                for (int pi = 0; pi < 4; pi++) {
                    const float4 v = *(const float4*)&sB[(((wn * 4 + pi) * 4 + kb + 1) * 32 + lane) * 4];
                    bf[2 * pi][0]     = __float_as_uint(v.x); bf[2 * pi][1]     = __float_as_uint(v.y);
                    bf[2 * pi + 1][0] = __float_as_uint(v.z); bf[2 * pi + 1][1] = __float_as_uint(v.w);
                }
            }
        }
        __syncwarp();
        if (lane == 0) mbar_arrive(emptyb + slot * 8);   // this warp done reading slot
    }

    // Epilogue
    #pragma unroll
    for (int mi = 0; mi < 4; mi++) {
        const int r0 = rowBlock + wm * 64 + mi * 16 + g;
        const int r1 = r0 + 8;
        float s0 = 1.f, s1 = 1.f;
        if (SCALE) { s0 = g_att[r0]; s1 = g_att[r1]; }
        float ss0 = 0.f, ss1 = 0.f;
        #pragma unroll
        for (int ni = 0; ni < 8; ni++) {
            const int c0 = colBlock + wn * 64 + ni * 8 + tg * 2;
            const float2 bb = *(const float2*)&bias[c0];
            float v00 = fmaxf(acc[mi][ni][0] + bb.x, 0.f);
            float v01 = fmaxf(acc[mi][ni][1] + bb.y, 0.f);
            float v10 = fmaxf(acc[mi][ni][2] + bb.x, 0.f);
            float v11 = fmaxf(acc[mi][ni][3] + bb.y, 0.f);
            if (SCALE) {
                *(float2*)&Cout[(size_t)r0 * NDIM + c0] = make_float2(v00 * s0, v01 * s0);
                *(float2*)&Cout[(size_t)r1 * NDIM + c0] = make_float2(v10 * s1, v11 * s1);
            } else {
                ss0 += v00 * v00 + v01 * v01;
                ss1 += v10 * v10 + v11 * v11;
                *(__nv_bfloat162*)&g_xp[(size_t)r0 * NDIM + c0] =
                    __float22bfloat162_rn(make_float2(v00, v01));
                *(__nv_bfloat162*)&g_xp[(size_t)r1 * NDIM + c0] =
                    __float22bfloat162_rn(make_float2(v10, v11));
            }
        }
        if (!SCALE) {
            ss0 += __shfl_xor_sync(0xffffffffu, ss0, 1);
            ss0 += __shfl_xor_sync(0xffffffffu, ss0, 2);
            ss1 += __shfl_xor_sync(0xffffffffu, ss1, 1);
            ss1 += __shfl_xor_sync(0xffffffffu, ss1, 2);
            if (tg == 0) {
                atomicAdd(&g_ss[r0], ss0);
                atomicAdd(&g_ss[r1], ss1);
            }
        }
    }
}

// ---------------- converter: B pair-frag-major + rna (+optional zeroing) --
__global__ void cvtB_kernel(const float* __restrict__ W, float* __restrict__ dst, int do_zero) {
    const int i    = blockIdx.x * blockDim.x + threadIdx.x;   // float4 idx
    const int lane = i & 31;
    const int kb   = (i >> 5) & 127;
    const int p    = i >> 12;
    const int col0 = p * 16 + (lane >> 2);
    const int c0   = kb * 8 + (lane & 3);
    float4 v;
    v.x = rna_tf32(W[(size_t)col0 * KDIM + c0]);
    v.y = rna_tf32(W[(size_t)col0 * KDIM + c0 + 4]);
    v.z = rna_tf32(W[(size_t)(col0 + 8) * KDIM + c0]);
    v.w = rna_tf32(W[(size_t)(col0 + 8) * KDIM + c0 + 4]);
    ((float4*)dst)[i] = v;
    if (do_zero) {
        if (i < M_ROWS) g_ss[i] = 0.f;
        if (i < BATCH * NDIM) g_ws[i] = 0.f;
    }
}

// ---------------- aux kernels --------------------------------------------
__global__ void inv_kernel() {
    const int i = blockIdx.x * 256 + threadIdx.x;
    g_inv[i] = 1.f / (sqrtf(g_ss[i]) + 1e-8f);
}
__global__ void msum_kernel(const float* __restrict__ mask) {
    int w = threadIdx.x >> 5, lane = threadIdx.x & 31;
    if (w >= BATCH) return;
    float s = 0.f;
    for (int n = lane; n < SEQ; n += 32) s += mask[n * BATCH + w];
    #pragma unroll
    for (int o = 16; o > 0; o >>= 1) s += __shfl_xor_sync(0xffffffffu, s, o);
    if (lane == 0) g_msum[w] = s;
}
__global__ void ws_kernel(const float* __restrict__ mask) {
    __shared__ float coef[128];
    const int b = blockIdx.x, n0 = blockIdx.y * 128, tid = threadIdx.x;
    if (tid < 128) coef[tid] = mask[(n0 + tid) * BATCH + b] * g_inv[b * SEQ + n0 + tid];
    __syncthreads();
    float acc[4] = {0.f, 0.f, 0.f, 0.f};
    const __nv_bfloat16* base = g_xp + (size_t)(b * SEQ + n0) * NDIM + tid * 4;
    #pragma unroll 2
    for (int j = 0; j < 128; j += 2) {
        const float cf0 = coef[j], cf1 = coef[j + 1];
        const __nv_bfloat162* r0 = (const __nv_bfloat162*)(base + (size_t)j * NDIM);
        const __nv_bfloat162* r1 = (const __nv_bfloat162*)(base + (size_t)(j + 1) * NDIM);
        const float2 a0 = __bfloat1622float2(r0[0]);
        const float2 a1 = __bfloat1622float2(r0[1]);
        const float2 b0 = __bfloat1622float2(r1[0]);
        const float2 b1 = __bfloat1622float2(r1[1]);
        acc[0] += cf0 * a0.x + cf1 * b0.x;
        acc[1] += cf0 * a0.y + cf1 * b0.y;
        acc[2] += cf0 * a1.x + cf1 * b1.x;
        acc[3] += cf0 * a1.y + cf1 * b1.y;
    }
    #pragma unroll
    for (int i = 0; i < 4; i++) atomicAdd(&g_ws[b * NDIM + tid * 4 + i], acc[i]);
}
__global__ void att_kernel() {
    int row = blockIdx.x * 8 + (threadIdx.x >> 5);
    int lane = threadIdx.x & 31;
    int b = row >> 11;
    const __nv_bfloat162* xr = (const __nv_bfloat162*)(g_xp + (size_t)row * NDIM);
    const float2* w = (const float2*)(g_ws + b * NDIM);
    float d = 0.f;
    #pragma unroll 4
    for (int i = lane; i < NDIM / 2; i += 32) {
        const float2 xv = __bfloat1622float2(xr[i]);
        const float2 wv = w[i];
        d += xv.x * wv.x + xv.y * wv.y;
    }
    #pragma unroll
    for (int o = 16; o > 0; o >>= 1) d += __shfl_xor_sync(0xffffffffu, d, o);
    if (lane == 0) g_att[row] = g_inv[row] * d / g_msum[b];
}

// ---------------- launch -------------------------------------------------
extern "C" void kernel_launch(void* const* d_in, const int* in_sizes, int n_in,
                              void* d_out, int out_size) {
    const float* x    = (const float*)d_in[0];
    const float* mask = (const float*)d_in[1];
    const float* Wp   = (const float*)d_in[2];
    const float* bp   = (const float*)d_in[3];
    const float* Wv   = (const float*)d_in[4];
    const float* bv   = (const float*)d_in[5];
    float* out = (float*)d_out;

    cudaFuncSetAttribute(gemm_relu_kernel<false>, cudaFuncAttributeMaxDynamicSharedMemorySize, SMEM_BYTES);
    cudaFuncSetAttribute(gemm_relu_kernel<true>,  cudaFuncAttributeMaxDynamicSharedMemorySize, SMEM_BYTES);

    float *wpf, *wvf;
    cudaGetSymbolAddress((void**)&wpf, g_wpf);
    cudaGetSymbolAddress((void**)&wvf, g_wvf);

    dim3 ggrid(NDIM / 128, M_ROWS / 128);   // (8, 256)

    cvtB_kernel<<<(NDIM * KDIM / 4) / 256, 256>>>(Wp, wpf, 1);        // 0 (+zero ss/ws)
    cvtB_kernel<<<(NDIM * KDIM / 4) / 256, 256>>>(Wv, wvf, 0);        // 1
    gemm_relu_kernel<false><<<ggrid, 128, SMEM_BYTES>>>(x, wpf, bp, nullptr);  // 2
    inv_kernel<<<M_ROWS / 256, 256>>>();                              // 3
    msum_kernel<<<1, 512>>>(mask);                                    // 4
    ws_kernel<<<dim3(BATCH, SEQ / 128), 256>>>(mask);                 // 5
    att_kernel<<<M_ROWS / 8, 256>>>();                                // 6
    gemm_relu_kernel<true><<<ggrid, 128, SMEM_BYTES>>>(x, wvf, bv, out);  // 7
}

// round 15
// speedup vs baseline: 1.0694x; 1.0694x over previous
#include <cuda_runtime.h>
#include <cuda_bf16.h>
#include <cstdint>

// Shapes (fixed)
#define BATCH   16
#define SEQ     2048
#define M_ROWS  (BATCH * SEQ)   // 32768
#define KDIM    1024
#define NDIM    1024

// GEMM tiling: block 128x128, 4 warps (warp tile 64x64), BK=32, 3-stage pipe
#define BK          32
#define NCHUNKS     (KDIM / BK)         // 32
#define NST         3
#define A_STAGE_B   16384               // 128 rows * 128B (canonical, swizzled)
#define B_STAGE_B   16384               // 8 pairs * 4 kb * 32 lanes * 16B
#define STAGE_B     (A_STAGE_B + B_STAGE_B)   // 32768
#define SMEM_BYTES  (NST * STAGE_B)           // 98304

// ---------------- scratch -----------------------------------------------
__device__ float g_wpf[NDIM * KDIM];               // Wp tf32, B-pair-frag-major
__device__ float g_wvf[NDIM * KDIM];               // Wv tf32, B-pair-frag-major
__device__ __nv_bfloat16 g_xp[(size_t)M_ROWS * NDIM];  // xp in bf16
__device__ float g_ss [M_ROWS];
__device__ float g_inv[M_ROWS];
__device__ float g_ws [BATCH * NDIM];
__device__ float g_att[M_ROWS];
__device__ float g_msum[BATCH];

// ---------------- helpers ------------------------------------------------
__device__ __forceinline__ uint32_t smem_u32(const void* p) {
    uint32_t a;
    asm("{ .reg .u64 t; cvta.to.shared.u64 t, %1; cvt.u32.u64 %0, t; }" : "=r"(a) : "l"(p));
    return a;
}
__device__ __forceinline__ void mma_tf32(float c[4], const uint32_t a[4], const uint32_t b[2]) {
    asm volatile(
        "mma.sync.aligned.m16n8k8.row.col.f32.tf32.tf32.f32 "
        "{%0,%1,%2,%3}, {%4,%5,%6,%7}, {%8,%9}, {%0,%1,%2,%3};\n"
        : "+f"(c[0]), "+f"(c[1]), "+f"(c[2]), "+f"(c[3])
        : "r"(a[0]), "r"(a[1]), "r"(a[2]), "r"(a[3]), "r"(b[0]), "r"(b[1]));
}
__device__ __forceinline__ void ldsm4(uint32_t a[4], uint32_t addr) {
    asm volatile("ldmatrix.sync.aligned.m8n8.x4.shared.b16 {%0,%1,%2,%3}, [%4];"
        : "=r"(a[0]), "=r"(a[1]), "=r"(a[2]), "=r"(a[3]) : "r"(addr));
}
__device__ __forceinline__ void cp16(uint32_t dst, const void* src) {
    asm volatile("cp.async.cg.shared.global [%0], [%1], 16;" :: "r"(dst), "l"(src) : "memory");
}
__device__ __forceinline__ void cp_commit() { asm volatile("cp.async.commit_group;" ::: "memory"); }
__device__ __forceinline__ void cp_wait1()  { asm volatile("cp.async.wait_group 1;" ::: "memory"); }
__device__ __forceinline__ void cp_wait0()  { asm volatile("cp.async.wait_group 0;" ::: "memory"); }
__device__ __forceinline__ float rna_tf32(float x) {
    asm("cvt.rna.tf32.f32 %0, %0;" : "+f"(x));
    return x;
}

// ---------------- pipelined tf32 GEMM (R11 structure, proven 298us) ------
// A: canonical [M,K] fp32 (x itself), SW128-swizzled rows, ldmatrix frags.
// B: pair-frag-major prepass (rna), float4 loads.
template<bool SCALE>
__global__ __launch_bounds__(128, 2) void gemm_relu_kernel(
    const float* __restrict__ A,
    const float* __restrict__ Bf,
    const float* __restrict__ bias,
    float* __restrict__ Cout)
{
    extern __shared__ float smemf[];
    const uint32_t sb = smem_u32(smemf);

    const int tid    = threadIdx.x;
    const int warpId = tid >> 5;
    const int lane   = tid & 31;
    const int wm     = warpId >> 1;   // 0..1
    const int wn     = warpId & 1;    // 0..1
    const int g      = lane >> 2;
    const int tg     = lane & 3;

    const int rowBlock = blockIdx.y * 128;
    const int colBlock = blockIdx.x * 128;
    const int p8base   = colBlock >> 4;

    const int roff  = (lane & 7) + (((lane >> 3) & 1) << 3);
    const int coff  = lane >> 4;
    const uint32_t xorm = (lane & 7) << 4;
    const uint32_t a_lane_base = (uint32_t)(wm * 64 + roff) * 128;

    float acc[4][8][4];
    #pragma unroll
    for (int mi = 0; mi < 4; mi++)
        #pragma unroll
        for (int ni = 0; ni < 8; ni++)
            #pragma unroll
            for (int r = 0; r < 4; r++) acc[mi][ni][r] = 0.f;

    auto load_stage = [&](int ck, int slot) {
        const uint32_t base = sb + slot * STAGE_B;
        const int kf0 = ck * BK;
        #pragma unroll
        for (int j = 0; j < 8; j++) {       // A: canonical rows, swizzled
            const int i   = tid + j * 128;
            const int row = i >> 3;
            const int kc  = i & 7;
            const uint32_t dst = base + (uint32_t)row * 128 + (((uint32_t)kc << 4) ^ ((row & 7) << 4));
            cp16(dst, A + (size_t)(rowBlock + row) * KDIM + kf0 + kc * 4);
        }
        const int kb0 = ck * 4;
        #pragma unroll
        for (int j = 0; j < 8; j++) {       // B: frag-major
            const int i   = tid + j * 128;
            const int pl  = i >> 7;
            const int kbl = (i >> 5) & 3;
            const int ln  = i & 31;
            const size_t src = ((size_t)((p8base + pl) * 128 + kb0 + kbl) * 32 + ln) * 4;
            cp16(base + A_STAGE_B + i * 16, Bf + src);
        }
        cp_commit();
    };

    auto compute_chunk = [&](int ks, bool prefetch) {
        const uint32_t sAu = sb + (ks % NST) * STAGE_B + a_lane_base;
        const float* sB = smemf + (ks % NST) * (STAGE_B / 4) + (A_STAGE_B / 4);

        uint32_t af[4][4];
        uint32_t bf[8][2];
        #pragma unroll
        for (int mi = 0; mi < 4; mi++)
            ldsm4(af[mi], sAu + (uint32_t)(mi * 16) * 128 + (((uint32_t)coff << 4) ^ xorm));
        #pragma unroll
        for (int pi = 0; pi < 4; pi++) {
            const float4 v = *(const float4*)&sB[(((wn * 4 + pi) * 4 + 0) * 32 + lane) * 4];
            bf[2 * pi][0]     = __float_as_uint(v.x); bf[2 * pi][1]     = __float_as_uint(v.y);
            bf[2 * pi + 1][0] = __float_as_uint(v.z); bf[2 * pi + 1][1] = __float_as_uint(v.w);
        }

        if (prefetch) load_stage(ks + 2, (ks + 2) % NST);

        #pragma unroll
        for (int kb = 0; kb < 4; kb++) {
            #pragma unroll
            for (int mi = 0; mi < 4; mi++)
                #pragma unroll
                for (int ni = 0; ni < 8; ni++)
                    mma_tf32(acc[mi][ni], af[mi], bf[ni]);
            if (kb < 3) {
                const uint32_t kin = (((uint32_t)(kb + 1) << 5) | ((uint32_t)coff << 4)) ^ xorm;
                #pragma unroll
                for (int mi = 0; mi < 4; mi++)
                    ldsm4(af[mi], sAu + (uint32_t)(mi * 16) * 128 + kin);
                #pragma unroll
                for (int pi = 0; pi < 4; pi++) {
                    const float4 v = *(const float4*)&sB[(((wn * 4 + pi) * 4 + kb + 1) * 32 + lane) * 4];
                    bf[2 * pi][0]     = __float_as_uint(v.x); bf[2 * pi][1]     = __float_as_uint(v.y);
                    bf[2 * pi + 1][0] = __float_as_uint(v.z); bf[2 * pi + 1][1] = __float_as_uint(v.w);
                }
            }
        }
    };

    load_stage(0, 0);
    load_stage(1, 1);

    for (int ks = 0; ks < NCHUNKS - 2; ks++) {
        cp_wait1();
        __syncthreads();
        compute_chunk(ks, true);
    }
    cp_wait1();
    __syncthreads();
    compute_chunk(NCHUNKS - 2, false);
    cp_wait0();
    __syncthreads();
    compute_chunk(NCHUNKS - 1, false);

    // Epilogue
    #pragma unroll
    for (int mi = 0; mi < 4; mi++) {
        const int r0 = rowBlock + wm * 64 + mi * 16 + g;
        const int r1 = r0 + 8;
        float s0 = 1.f, s1 = 1.f;
        if (SCALE) { s0 = g_att[r0]; s1 = g_att[r1]; }
        float ss0 = 0.f, ss1 = 0.f;
        #pragma unroll
        for (int ni = 0; ni < 8; ni++) {
            const int c0 = colBlock + wn * 64 + ni * 8 + tg * 2;
            const float2 bb = *(const float2*)&bias[c0];
            float v00 = fmaxf(acc[mi][ni][0] + bb.x, 0.f);
            float v01 = fmaxf(acc[mi][ni][1] + bb.y, 0.f);
            float v10 = fmaxf(acc[mi][ni][2] + bb.x, 0.f);
            float v11 = fmaxf(acc[mi][ni][3] + bb.y, 0.f);
            if (SCALE) {
                *(float2*)&Cout[(size_t)r0 * NDIM + c0] = make_float2(v00 * s0, v01 * s0);
                *(float2*)&Cout[(size_t)r1 * NDIM + c0] = make_float2(v10 * s1, v11 * s1);
            } else {
                ss0 += v00 * v00 + v01 * v01;
                ss1 += v10 * v10 + v11 * v11;
                *(__nv_bfloat162*)&g_xp[(size_t)r0 * NDIM + c0] =
                    __float22bfloat162_rn(make_float2(v00, v01));
                *(__nv_bfloat162*)&g_xp[(size_t)r1 * NDIM + c0] =
                    __float22bfloat162_rn(make_float2(v10, v11));
            }
        }
        if (!SCALE) {
            ss0 += __shfl_xor_sync(0xffffffffu, ss0, 1);
            ss0 += __shfl_xor_sync(0xffffffffu, ss0, 2);
            ss1 += __shfl_xor_sync(0xffffffffu, ss1, 1);
            ss1 += __shfl_xor_sync(0xffffffffu, ss1, 2);
            if (tg == 0) {
                atomicAdd(&g_ss[r0], ss0);
                atomicAdd(&g_ss[r1], ss1);
            }
        }
    }
}

// ---------------- converter: B pair-frag-major + rna (+optional zeroing) --
__global__ void cvtB_kernel(const float* __restrict__ W, float* __restrict__ dst, int do_zero) {
    const int i    = blockIdx.x * blockDim.x + threadIdx.x;   // float4 idx
    const int lane = i & 31;
    const int kb   = (i >> 5) & 127;
    const int p    = i >> 12;
    const int col0 = p * 16 + (lane >> 2);
    const int c0   = kb * 8 + (lane & 3);
    float4 v;
    v.x = rna_tf32(W[(size_t)col0 * KDIM + c0]);
    v.y = rna_tf32(W[(size_t)col0 * KDIM + c0 + 4]);
    v.z = rna_tf32(W[(size_t)(col0 + 8) * KDIM + c0]);
    v.w = rna_tf32(W[(size_t)(col0 + 8) * KDIM + c0 + 4]);
    ((float4*)dst)[i] = v;
    if (do_zero) {
        if (i < M_ROWS) g_ss[i] = 0.f;
        if (i < BATCH * NDIM) g_ws[i] = 0.f;
    }
}

// ---------------- aux kernels --------------------------------------------
// inv for all rows; block 0's 8 warps each compute TWO msum batches (w, w+8).
__global__ void inv_msum_kernel(const float* __restrict__ mask) {
    const int i = blockIdx.x * 256 + threadIdx.x;
    g_inv[i] = 1.f / (sqrtf(g_ss[i]) + 1e-8f);
    if (blockIdx.x == 0) {
        const int w = threadIdx.x >> 5, lane = threadIdx.x & 31;   // w = 0..7
        #pragma unroll
        for (int half = 0; half < 2; half++) {
            const int b = w + half * 8;                            // 0..15
            float s = 0.f;
            for (int n = lane; n < SEQ; n += 32) s += mask[n * BATCH + b];
            #pragma unroll
            for (int o = 16; o > 0; o >>= 1) s += __shfl_xor_sync(0xffffffffu, s, o);
            if (lane == 0) g_msum[b] = s;
        }
    }
}
__global__ void ws_kernel(const float* __restrict__ mask) {
    __shared__ float coef[128];
    const int b = blockIdx.x, n0 = blockIdx.y * 128, tid = threadIdx.x;
    if (tid < 128) coef[tid] = mask[(n0 + tid) * BATCH + b] * g_inv[b * SEQ + n0 + tid];
    __syncthreads();
    float acc[4] = {0.f, 0.f, 0.f, 0.f};
    const __nv_bfloat16* base = g_xp + (size_t)(b * SEQ + n0) * NDIM + tid * 4;
    #pragma unroll 2
    for (int j = 0; j < 128; j += 2) {
        const float cf0 = coef[j], cf1 = coef[j + 1];
        const uint2 p0 = *(const uint2*)(base + (size_t)j * NDIM);
        const uint2 p1 = *(const uint2*)(base + (size_t)(j + 1) * NDIM);
        const float2 a0 = __bfloat1622float2(*(const __nv_bfloat162*)&p0.x);
        const float2 a1 = __bfloat1622float2(*(const __nv_bfloat162*)&p0.y);
        const float2 b0 = __bfloat1622float2(*(const __nv_bfloat162*)&p1.x);
        const float2 b1 = __bfloat1622float2(*(const __nv_bfloat162*)&p1.y);
        acc[0] += cf0 * a0.x + cf1 * b0.x;
        acc[1] += cf0 * a0.y + cf1 * b0.y;
        acc[2] += cf0 * a1.x + cf1 * b1.x;
        acc[3] += cf0 * a1.y + cf1 * b1.y;
    }
    #pragma unroll
    for (int i = 0; i < 4; i++) atomicAdd(&g_ws[b * NDIM + tid * 4 + i], acc[i]);
}
__global__ void att_kernel() {
    int row = blockIdx.x * 8 + (threadIdx.x >> 5);
    int lane = threadIdx.x & 31;
    int b = row >> 11;
    const __nv_bfloat162* xr = (const __nv_bfloat162*)(g_xp + (size_t)row * NDIM);
    const float2* w = (const float2*)(g_ws + b * NDIM);
    float d = 0.f;
    #pragma unroll 4
    for (int i = lane; i < NDIM / 2; i += 32) {
        const float2 xv = __bfloat1622float2(xr[i]);
        const float2 wv = w[i];
        d += xv.x * wv.x + xv.y * wv.y;
    }
    #pragma unroll
    for (int o = 16; o > 0; o >>= 1) d += __shfl_xor_sync(0xffffffffu, d, o);
    if (lane == 0) g_att[row] = g_inv[row] * d / g_msum[b];
}

// ---------------- launch -------------------------------------------------
extern "C" void kernel_launch(void* const* d_in, const int* in_sizes, int n_in,
                              void* d_out, int out_size) {
    const float* x    = (const float*)d_in[0];
    const float* mask = (const float*)d_in[1];
    const float* Wp   = (const float*)d_in[2];
    const float* bp   = (const float*)d_in[3];
    const float* Wv   = (const float*)d_in[4];
    const float* bv   = (const float*)d_in[5];
    float* out = (float*)d_out;

    cudaFuncSetAttribute(gemm_relu_kernel<false>, cudaFuncAttributeMaxDynamicSharedMemorySize, SMEM_BYTES);
    cudaFuncSetAttribute(gemm_relu_kernel<true>,  cudaFuncAttributeMaxDynamicSharedMemorySize, SMEM_BYTES);

    float *wpf, *wvf;
    cudaGetSymbolAddress((void**)&wpf, g_wpf);
    cudaGetSymbolAddress((void**)&wvf, g_wvf);

    dim3 ggrid(NDIM / 128, M_ROWS / 128);   // (8, 256)

    cvtB_kernel<<<(NDIM * KDIM / 4) / 256, 256>>>(Wp, wpf, 1);        // 0 (+zero ss/ws)
    cvtB_kernel<<<(NDIM * KDIM / 4) / 256, 256>>>(Wv, wvf, 0);        // 1
    gemm_relu_kernel<false><<<ggrid, 128, SMEM_BYTES>>>(x, wpf, bp, nullptr);  // 2
    inv_msum_kernel<<<M_ROWS / 256, 256>>>(mask);                     // 3
    ws_kernel<<<dim3(BATCH, SEQ / 128), 256>>>(mask);                 // 4
    att_kernel<<<M_ROWS / 8, 256>>>();                                // 5
    gemm_relu_kernel<true><<<ggrid, 128, SMEM_BYTES>>>(x, wvf, bv, out);  // 6
}

// round 16
// speedup vs baseline: 1.0823x; 1.0121x over previous
#include <cuda_runtime.h>
#include <cuda_bf16.h>
#include <cstdint>

// Shapes (fixed)
#define BATCH   16
#define SEQ     2048
#define M_ROWS  (BATCH * SEQ)   // 32768
#define KDIM    1024
#define NDIM    1024

// GEMM tiling: block 128x128, 4 warps (warp tile 64x64), BK=32, 3-stage pipe
#define BK          32
#define NCHUNKS     (KDIM / BK)         // 32
#define NST         3
#define A_STAGE_B   16384               // 128 rows * 128B (canonical, swizzled)
#define B_STAGE_B   16384               // 8 pairs * 4 kb * 32 lanes * 16B
#define STAGE_B     (A_STAGE_B + B_STAGE_B)   // 32768
#define SMEM_BYTES  (NST * STAGE_B)           // 98304

// ---------------- scratch -----------------------------------------------
__device__ float g_wpf[NDIM * KDIM];               // Wp tf32, B-pair-frag-major
__device__ float g_wvf[NDIM * KDIM];               // Wv tf32, B-pair-frag-major
__device__ __nv_bfloat16 g_xp[(size_t)M_ROWS * NDIM];  // xp in bf16
__device__ float g_ss [M_ROWS];
__device__ float g_inv[M_ROWS];
__device__ float g_ws [BATCH * NDIM];
__device__ float g_att[M_ROWS];
__device__ float g_msum[BATCH];

// ---------------- helpers ------------------------------------------------
__device__ __forceinline__ uint32_t smem_u32(const void* p) {
    uint32_t a;
    asm("{ .reg .u64 t; cvta.to.shared.u64 t, %1; cvt.u32.u64 %0, t; }" : "=r"(a) : "l"(p));
    return a;
}
__device__ __forceinline__ void mma_tf32(float c[4], const uint32_t a[4], const uint32_t b[2]) {
    asm volatile(
        "mma.sync.aligned.m16n8k8.row.col.f32.tf32.tf32.f32 "
        "{%0,%1,%2,%3}, {%4,%5,%6,%7}, {%8,%9}, {%0,%1,%2,%3};\n"
        : "+f"(c[0]), "+f"(c[1]), "+f"(c[2]), "+f"(c[3])
        : "r"(a[0]), "r"(a[1]), "r"(a[2]), "r"(a[3]), "r"(b[0]), "r"(b[1]));
}
__device__ __forceinline__ void ldsm4(uint32_t a[4], uint32_t addr) {
    asm volatile("ldmatrix.sync.aligned.m8n8.x4.shared.b16 {%0,%1,%2,%3}, [%4];"
        : "=r"(a[0]), "=r"(a[1]), "=r"(a[2]), "=r"(a[3]) : "r"(addr));
}
__device__ __forceinline__ void cp16(uint32_t dst, const void* src) {
    asm volatile("cp.async.cg.shared.global [%0], [%1], 16;" :: "r"(dst), "l"(src) : "memory");
}
__device__ __forceinline__ void cp_commit() { asm volatile("cp.async.commit_group;" ::: "memory"); }
__device__ __forceinline__ void cp_wait1()  { asm volatile("cp.async.wait_group 1;" ::: "memory"); }
__device__ __forceinline__ void cp_wait0()  { asm volatile("cp.async.wait_group 0;" ::: "memory"); }
__device__ __forceinline__ float rna_tf32(float x) {
    asm("cvt.rna.tf32.f32 %0, %0;" : "+f"(x));
    return x;
}

// ---------------- pipelined tf32 GEMM (proven 298us config) --------------
// A: canonical [M,K] fp32 (x itself), SW128-swizzled rows, ldmatrix frags.
// B: pair-frag-major prepass (rna), float4 loads.
template<bool SCALE>
__global__ __launch_bounds__(128, 2) void gemm_relu_kernel(
    const float* __restrict__ A,
    const float* __restrict__ Bf,
    const float* __restrict__ bias,
    float* __restrict__ Cout)
{
    extern __shared__ float smemf[];
    const uint32_t sb = smem_u32(smemf);

    const int tid    = threadIdx.x;
    const int warpId = tid >> 5;
    const int lane   = tid & 31;
    const int wm     = warpId >> 1;   // 0..1
    const int wn     = warpId & 1;    // 0..1
    const int g      = lane >> 2;
    const int tg     = lane & 3;

    const int rowBlock = blockIdx.y * 128;
    const int colBlock = blockIdx.x * 128;
    const int p8base   = colBlock >> 4;

    const int roff  = (lane & 7) + (((lane >> 3) & 1) << 3);
    const int coff  = lane >> 4;
    const uint32_t xorm = (lane & 7) << 4;
    const uint32_t a_lane_base = (uint32_t)(wm * 64 + roff) * 128;

    float acc[4][8][4];
    #pragma unroll
    for (int mi = 0; mi < 4; mi++)
        #pragma unroll
        for (int ni = 0; ni < 8; ni++)
            #pragma unroll
            for (int r = 0; r < 4; r++) acc[mi][ni][r] = 0.f;

    auto load_stage = [&](int ck, int slot) {
        const uint32_t base = sb + slot * STAGE_B;
        const int kf0 = ck * BK;
        #pragma unroll
        for (int j = 0; j < 8; j++) {       // A: canonical rows, swizzled
            const int i   = tid + j * 128;
            const int row = i >> 3;
            const int kc  = i & 7;
            const uint32_t dst = base + (uint32_t)row * 128 + (((uint32_t)kc << 4) ^ ((row & 7) << 4));
            cp16(dst, A + (size_t)(rowBlock + row) * KDIM + kf0 + kc * 4);
        }
        const int kb0 = ck * 4;
        #pragma unroll
        for (int j = 0; j < 8; j++) {       // B: frag-major
            const int i   = tid + j * 128;
            const int pl  = i >> 7;
            const int kbl = (i >> 5) & 3;
            const int ln  = i & 31;
            const size_t src = ((size_t)((p8base + pl) * 128 + kb0 + kbl) * 32 + ln) * 4;
            cp16(base + A_STAGE_B + i * 16, Bf + src);
        }
        cp_commit();
    };

    auto compute_chunk = [&](int ks, bool prefetch) {
        const uint32_t sAu = sb + (ks % NST) * STAGE_B + a_lane_base;
        const float* sB = smemf + (ks % NST) * (STAGE_B / 4) + (A_STAGE_B / 4);

        uint32_t af[4][4];
        uint32_t bf[8][2];
        #pragma unroll
        for (int mi = 0; mi < 4; mi++)
            ldsm4(af[mi], sAu + (uint32_t)(mi * 16) * 128 + (((uint32_t)coff << 4) ^ xorm));
        #pragma unroll
        for (int pi = 0; pi < 4; pi++) {
            const float4 v = *(const float4*)&sB[(((wn * 4 + pi) * 4 + 0) * 32 + lane) * 4];
            bf[2 * pi][0]     = __float_as_uint(v.x); bf[2 * pi][1]     = __float_as_uint(v.y);
            bf[2 * pi + 1][0] = __float_as_uint(v.z); bf[2 * pi + 1][1] = __float_as_uint(v.w);
        }

        if (prefetch) load_stage(ks + 2, (ks + 2) % NST);

        #pragma unroll
        for (int kb = 0; kb < 4; kb++) {
            #pragma unroll
            for (int mi = 0; mi < 4; mi++)
                #pragma unroll
                for (int ni = 0; ni < 8; ni++)
                    mma_tf32(acc[mi][ni], af[mi], bf[ni]);
            if (kb < 3) {
                const uint32_t kin = (((uint32_t)(kb + 1) << 5) | ((uint32_t)coff << 4)) ^ xorm;
                #pragma unroll
                for (int mi = 0; mi < 4; mi++)
                    ldsm4(af[mi], sAu + (uint32_t)(mi * 16) * 128 + kin);
                #pragma unroll
                for (int pi = 0; pi < 4; pi++) {
                    const float4 v = *(const float4*)&sB[(((wn * 4 + pi) * 4 + kb + 1) * 32 + lane) * 4];
                    bf[2 * pi][0]     = __float_as_uint(v.x); bf[2 * pi][1]     = __float_as_uint(v.y);
                    bf[2 * pi + 1][0] = __float_as_uint(v.z); bf[2 * pi + 1][1] = __float_as_uint(v.w);
                }
            }
        }
    };

    load_stage(0, 0);
    load_stage(1, 1);

    for (int ks = 0; ks < NCHUNKS - 2; ks++) {
        cp_wait1();
        __syncthreads();
        compute_chunk(ks, true);
    }
    cp_wait1();
    __syncthreads();
    compute_chunk(NCHUNKS - 2, false);
    cp_wait0();
    __syncthreads();
    compute_chunk(NCHUNKS - 1, false);

    // Epilogue
    #pragma unroll
    for (int mi = 0; mi < 4; mi++) {
        const int r0 = rowBlock + wm * 64 + mi * 16 + g;
        const int r1 = r0 + 8;
        float s0 = 1.f, s1 = 1.f;
        if (SCALE) { s0 = g_att[r0]; s1 = g_att[r1]; }
        float ss0 = 0.f, ss1 = 0.f;
        #pragma unroll
        for (int ni = 0; ni < 8; ni++) {
            const int c0 = colBlock + wn * 64 + ni * 8 + tg * 2;
            const float2 bb = *(const float2*)&bias[c0];
            float v00 = fmaxf(acc[mi][ni][0] + bb.x, 0.f);
            float v01 = fmaxf(acc[mi][ni][1] + bb.y, 0.f);
            float v10 = fmaxf(acc[mi][ni][2] + bb.x, 0.f);
            float v11 = fmaxf(acc[mi][ni][3] + bb.y, 0.f);
            if (SCALE) {
                *(float2*)&Cout[(size_t)r0 * NDIM + c0] = make_float2(v00 * s0, v01 * s0);
                *(float2*)&Cout[(size_t)r1 * NDIM + c0] = make_float2(v10 * s1, v11 * s1);
            } else {
                ss0 += v00 * v00 + v01 * v01;
                ss1 += v10 * v10 + v11 * v11;
                *(__nv_bfloat162*)&g_xp[(size_t)r0 * NDIM + c0] =
                    __float22bfloat162_rn(make_float2(v00, v01));
                *(__nv_bfloat162*)&g_xp[(size_t)r1 * NDIM + c0] =
                    __float22bfloat162_rn(make_float2(v10, v11));
            }
        }
        if (!SCALE) {
            ss0 += __shfl_xor_sync(0xffffffffu, ss0, 1);
            ss0 += __shfl_xor_sync(0xffffffffu, ss0, 2);
            ss1 += __shfl_xor_sync(0xffffffffu, ss1, 1);
            ss1 += __shfl_xor_sync(0xffffffffu, ss1, 2);
            if (tg == 0) {
                atomicAdd(&g_ss[r0], ss0);
                atomicAdd(&g_ss[r1], ss1);
            }
        }
    }
}

// ---------------- converter: B pair-frag-major + rna (+optional zeroing) --
__global__ void cvtB_kernel(const float* __restrict__ W, float* __restrict__ dst, int do_zero) {
    const int i    = blockIdx.x * blockDim.x + threadIdx.x;   // float4 idx
    const int lane = i & 31;
    const int kb   = (i >> 5) & 127;
    const int p    = i >> 12;
    const int col0 = p * 16 + (lane >> 2);
    const int c0   = kb * 8 + (lane & 3);
    float4 v;
    v.x = rna_tf32(W[(size_t)col0 * KDIM + c0]);
    v.y = rna_tf32(W[(size_t)col0 * KDIM + c0 + 4]);
    v.z = rna_tf32(W[(size_t)(col0 + 8) * KDIM + c0]);
    v.w = rna_tf32(W[(size_t)(col0 + 8) * KDIM + c0 + 4]);
    ((float4*)dst)[i] = v;
    if (do_zero) {
        if (i < M_ROWS) g_ss[i] = 0.f;
        if (i < BATCH * NDIM) g_ws[i] = 0.f;
    }
}

// ---------------- aux kernels --------------------------------------------
__global__ void inv_kernel() {
    const int i = blockIdx.x * 256 + threadIdx.x;
    g_inv[i] = 1.f / (sqrtf(g_ss[i]) + 1e-8f);
}
// Coalesced msum: one block, 512 threads. Thread t reads mask[t], mask[t+512],...
// 512 % 16 == 0 so each thread stays on column t & 15. shfl_xor(16) merges the
// two same-column lanes in a warp; 16x16 smem pass finishes across warps.
__global__ void msum_kernel(const float* __restrict__ mask) {
    __shared__ float part[16][17];
    const int t = threadIdx.x;                 // 0..511
    const int lane = t & 31, w = t >> 5;       // 16 warps
    float s = 0.f;
    #pragma unroll 8
    for (int i = t; i < SEQ * BATCH; i += 512) s += mask[i];
    s += __shfl_xor_sync(0xffffffffu, s, 16);  // lanes l, l^16 share column l&15
    if (lane < 16) part[w][lane] = s;
    __syncthreads();
    if (t < 16) {
        float tot = 0.f;
        #pragma unroll
        for (int ww = 0; ww < 16; ww++) tot += part[ww][t];
        g_msum[t] = tot;
    }
}
__global__ void ws_kernel(const float* __restrict__ mask) {
    __shared__ float coef[128];
    const int b = blockIdx.x, n0 = blockIdx.y * 128, tid = threadIdx.x;
    if (tid < 128) coef[tid] = mask[(n0 + tid) * BATCH + b] * g_inv[b * SEQ + n0 + tid];
    __syncthreads();
    float acc[4] = {0.f, 0.f, 0.f, 0.f};
    const __nv_bfloat16* base = g_xp + (size_t)(b * SEQ + n0) * NDIM + tid * 4;
    #pragma unroll 2
    for (int j = 0; j < 128; j += 2) {
        const float cf0 = coef[j], cf1 = coef[j + 1];
        const uint2 p0 = *(const uint2*)(base + (size_t)j * NDIM);
        const uint2 p1 = *(const uint2*)(base + (size_t)(j + 1) * NDIM);
        const float2 a0 = __bfloat1622float2(*(const __nv_bfloat162*)&p0.x);
        const float2 a1 = __bfloat1622float2(*(const __nv_bfloat162*)&p0.y);
        const float2 b0 = __bfloat1622float2(*(const __nv_bfloat162*)&p1.x);
        const float2 b1 = __bfloat1622float2(*(const __nv_bfloat162*)&p1.y);
        acc[0] += cf0 * a0.x + cf1 * b0.x;
        acc[1] += cf0 * a0.y + cf1 * b0.y;
        acc[2] += cf0 * a1.x + cf1 * b1.x;
        acc[3] += cf0 * a1.y + cf1 * b1.y;
    }
    #pragma unroll
    for (int i = 0; i < 4; i++) atomicAdd(&g_ws[b * NDIM + tid * 4 + i], acc[i]);
}
__global__ void att_kernel() {
    int row = blockIdx.x * 8 + (threadIdx.x >> 5);
    int lane = threadIdx.x & 31;
    int b = row >> 11;
    const __nv_bfloat162* xr = (const __nv_bfloat162*)(g_xp + (size_t)row * NDIM);
    const float2* w = (const float2*)(g_ws + b * NDIM);
    float d = 0.f;
    #pragma unroll 4
    for (int i = lane; i < NDIM / 2; i += 32) {
        const float2 xv = __bfloat1622float2(xr[i]);
        const float2 wv = w[i];
        d += xv.x * wv.x + xv.y * wv.y;
    }
    #pragma unroll
    for (int o = 16; o > 0; o >>= 1) d += __shfl_xor_sync(0xffffffffu, d, o);
    if (lane == 0) g_att[row] = g_inv[row] * d / g_msum[b];
}

// ---------------- launch -------------------------------------------------
extern "C" void kernel_launch(void* const* d_in, const int* in_sizes, int n_in,
                              void* d_out, int out_size) {
    const float* x    = (const float*)d_in[0];
    const float* mask = (const float*)d_in[1];
    const float* Wp   = (const float*)d_in[2];
    const float* bp   = (const float*)d_in[3];
    const float* Wv   = (const float*)d_in[4];
    const float* bv   = (const float*)d_in[5];
    float* out = (float*)d_out;

    cudaFuncSetAttribute(gemm_relu_kernel<false>, cudaFuncAttributeMaxDynamicSharedMemorySize, SMEM_BYTES);
    cudaFuncSetAttribute(gemm_relu_kernel<true>,  cudaFuncAttributeMaxDynamicSharedMemorySize, SMEM_BYTES);

    float *wpf, *wvf;
    cudaGetSymbolAddress((void**)&wpf, g_wpf);
    cudaGetSymbolAddress((void**)&wvf, g_wvf);

    dim3 ggrid(NDIM / 128, M_ROWS / 128);   // (8, 256)

    msum_kernel<<<1, 512>>>(mask);                                    // 0 (mask-only dep)
    cvtB_kernel<<<(NDIM * KDIM / 4) / 256, 256>>>(Wp, wpf, 1);        // 1 (+zero ss/ws)
    cvtB_kernel<<<(NDIM * KDIM / 4) / 256, 256>>>(Wv, wvf, 0);        // 2
    gemm_relu_kernel<false><<<ggrid, 128, SMEM_BYTES>>>(x, wpf, bp, nullptr);  // 3
    inv_kernel<<<M_ROWS / 256, 256>>>();                              // 4
    ws_kernel<<<dim3(BATCH, SEQ / 128), 256>>>(mask);                 // 5
    att_kernel<<<M_ROWS / 8, 256>>>();                                // 6
    gemm_relu_kernel<true><<<ggrid, 128, SMEM_BYTES>>>(x, wvf, bv, out);  // 7
}